// round 6
// baseline (speedup 1.0000x reference)
#include <cuda_runtime.h>

#define NN 1024
#define BB 128
#define KS 8              // split-K factor
#define KCHUNK (NN / KS)  // 128

// Scratch (static device globals; no allocation)
__device__ float g_EWt[NN * NN];        // EWt[k][i] = exp(W[i][k])
__device__ float g_part[32 * NN];       // per-i-tile column partial sums
__device__ float g_c[NN];               // c[k] = log sum_i exp(W[i][k])
__device__ float g_At[NN * BB];         // At[k][b] = exp(la[b][k] - c[k] - m[b])
__device__ float g_m[BB];               // m[b]
__device__ float g_ps[KS * BB * NN];    // split-K partial sums

// ---------------------------------------------------------------------------
// k1: tiled transpose + exp + column partial sums
// grid (32 k-tiles, 32 i-tiles), block (32, 8)
// ---------------------------------------------------------------------------
__global__ void k1_exp_transpose(const float* __restrict__ W) {
    __shared__ float sm[32][33];
    const int k0 = blockIdx.x * 32, i0 = blockIdx.y * 32;
    const int tx = threadIdx.x, ty = threadIdx.y;

#pragma unroll
    for (int j = 0; j < 4; j++) {
        int il = ty + 8 * j;
        sm[il][tx] = __expf(W[(size_t)(i0 + il) * NN + (k0 + tx)]);
    }
    __syncthreads();

#pragma unroll
    for (int j = 0; j < 4; j++) {
        int kl = ty + 8 * j;
        g_EWt[(size_t)(k0 + kl) * NN + (i0 + tx)] = sm[tx][kl];
    }

    float s = 0.f;
#pragma unroll
    for (int j = 0; j < 4; j++) s += sm[ty + 8 * j][tx];

    __shared__ float red[8][32];
    red[ty][tx] = s;
    __syncthreads();
    if (ty == 0) {
        float t = 0.f;
#pragma unroll
        for (int y = 0; y < 8; y++) t += red[y][tx];
        g_part[blockIdx.y * NN + (k0 + tx)] = t;
    }
}

// ---------------------------------------------------------------------------
// k2: c[k] = log(sum of 32 partials)
// ---------------------------------------------------------------------------
__global__ void k2_colnorm() {
    int k = blockIdx.x * 256 + threadIdx.x;
    float s = 0.f;
#pragma unroll
    for (int t = 0; t < 32; t++) s += g_part[t * NN + k];
    g_c[k] = logf(s);
}

// ---------------------------------------------------------------------------
// k3: per-batch m[b] + At[k][b] = exp(la - c - m)
// ---------------------------------------------------------------------------
__global__ void k3_alpha(const float* __restrict__ la) {
    const int b = blockIdx.x, t = threadIdx.x;
    float4 lv = reinterpret_cast<const float4*>(la + (size_t)b * NN)[t];
    float4 cv = reinterpret_cast<const float4*>(g_c)[t];
    float v0 = lv.x - cv.x, v1 = lv.y - cv.y, v2 = lv.z - cv.z, v3 = lv.w - cv.w;
    float mx = fmaxf(fmaxf(v0, v1), fmaxf(v2, v3));
#pragma unroll
    for (int o = 16; o > 0; o >>= 1) mx = fmaxf(mx, __shfl_xor_sync(0xffffffffu, mx, o));
    __shared__ float wred[8];
    if ((t & 31) == 0) wred[t >> 5] = mx;
    __syncthreads();
    float m2 = wred[0];
#pragma unroll
    for (int w = 1; w < 8; w++) m2 = fmaxf(m2, wred[w]);

    const int k = 4 * t;
    g_At[(size_t)(k + 0) * BB + b] = __expf(v0 - m2);
    g_At[(size_t)(k + 1) * BB + b] = __expf(v1 - m2);
    g_At[(size_t)(k + 2) * BB + b] = __expf(v2 - m2);
    g_At[(size_t)(k + 3) * BB + b] = __expf(v3 - m2);
    if (t == 0) g_m[b] = m2;
}

// ---------------------------------------------------------------------------
// k4: split-K GEMM partial:  ps[z][b][i] = sum_{k in chunk z} At[k][b]*EWt[k][i]
// BM=32 (b), BN=64 (i), BK=32, 128 threads, 4x4 register tile, double-buffered
// grid (16 i-tiles, 4 b-tiles, KS k-chunks) = 512 blocks
// ---------------------------------------------------------------------------
__global__ void __launch_bounds__(128) k4_gemm() {
    __shared__ float As[2][32][36];   // [k][b]  (32 + 4 pad)
    __shared__ float Es[2][32][68];   // [k][i]  (64 + 4 pad)
    const int i0 = blockIdx.x * 64, b0 = blockIdx.y * 32;
    const int kbase = blockIdx.z * KCHUNK;
    const int tid = threadIdx.x;
    const int tm = tid & 7;            // 8 groups of 4 b-rows
    const int tn = tid >> 3;           // 16 groups of 4 i-cols

    float4 ra[2], re[4];

    // global prefetch of one BK=32 sub-chunk starting at k0
#define LOADG(k0)                                                                 \
    {                                                                             \
        _Pragma("unroll") for (int q = 0; q < 2; q++) {                           \
            int idx = tid + q * 128, r = idx >> 3, f = idx & 7;                   \
            ra[q] = *reinterpret_cast<const float4*>(                             \
                &g_At[(size_t)((k0) + r) * BB + b0 + f * 4]);                     \
        }                                                                         \
        _Pragma("unroll") for (int p = 0; p < 4; p++) {                           \
            int idx = tid + p * 128, r = idx >> 4, f = idx & 15;                  \
            re[p] = *reinterpret_cast<const float4*>(                             \
                &g_EWt[(size_t)((k0) + r) * NN + i0 + f * 4]);                    \
        }                                                                         \
    }

#define STORES(bf)                                                                \
    {                                                                             \
        _Pragma("unroll") for (int q = 0; q < 2; q++) {                           \
            int idx = tid + q * 128, r = idx >> 3, f = idx & 7;                   \
            *reinterpret_cast<float4*>(&As[bf][r][f * 4]) = ra[q];                \
        }                                                                         \
        _Pragma("unroll") for (int p = 0; p < 4; p++) {                           \
            int idx = tid + p * 128, r = idx >> 4, f = idx & 15;                  \
            *reinterpret_cast<float4*>(&Es[bf][r][f * 4]) = re[p];                \
        }                                                                         \
    }

    LOADG(kbase);
    STORES(0);
    __syncthreads();

    float acc[4][4];
#pragma unroll
    for (int r = 0; r < 4; r++)
#pragma unroll
        for (int s = 0; s < 4; s++) acc[r][s] = 0.f;

    const int NSUB = KCHUNK / 32;  // 4
    int buf = 0;
    for (int c = 0; c < NSUB; c++) {
        if (c + 1 < NSUB) LOADG(kbase + (c + 1) * 32);
#pragma unroll
        for (int kk = 0; kk < 32; kk++) {
            float4 a = *reinterpret_cast<const float4*>(&As[buf][kk][tm * 4]);
            float4 e = *reinterpret_cast<const float4*>(&Es[buf][kk][tn * 4]);
            float av[4] = {a.x, a.y, a.z, a.w};
            float ev[4] = {e.x, e.y, e.z, e.w};
#pragma unroll
            for (int r = 0; r < 4; r++)
#pragma unroll
                for (int s = 0; s < 4; s++) acc[r][s] = fmaf(av[r], ev[s], acc[r][s]);
        }
        if (c + 1 < NSUB) {
            __syncthreads();
            STORES(buf ^ 1);
            __syncthreads();
            buf ^= 1;
        }
    }

    // write fp32 partials (no log here)
    float* ps = g_ps + (size_t)blockIdx.z * BB * NN;
#pragma unroll
    for (int r = 0; r < 4; r++) {
        const int b = b0 + tm * 4 + r;
        float4 o = make_float4(acc[r][0], acc[r][1], acc[r][2], acc[r][3]);
        *reinterpret_cast<float4*>(&ps[(size_t)b * NN + i0 + tn * 4]) = o;
    }
#undef LOADG
#undef STORES
}

// ---------------------------------------------------------------------------
// k5: reduce KS partials, out = log(sum) + m[b]
// grid 128, block 256; one float4 per thread
// ---------------------------------------------------------------------------
__global__ void k5_reduce(float* __restrict__ out) {
    const int idx = blockIdx.x * 256 + threadIdx.x;  // float4 index, 32768 total
    const int b = idx >> 8;                          // 256 float4 per b-row
    const float4* p = reinterpret_cast<const float4*>(g_ps);
    float4 s = p[idx];
#pragma unroll
    for (int z = 1; z < KS; z++) {
        float4 v = p[(size_t)z * (BB * NN / 4) + idx];
        s.x += v.x; s.y += v.y; s.z += v.z; s.w += v.w;
    }
    const float mb = g_m[b];
    float4 o;
    o.x = logf(s.x) + mb;
    o.y = logf(s.y) + mb;
    o.z = logf(s.z) + mb;
    o.w = logf(s.w) + mb;
    reinterpret_cast<float4*>(out)[idx] = o;
}

// ---------------------------------------------------------------------------
extern "C" void kernel_launch(void* const* d_in, const int* in_sizes, int n_in,
                              void* d_out, int out_size) {
    const float* la;
    const float* W;
    if (in_sizes[0] == BB * NN) {
        la = (const float*)d_in[0];
        W  = (const float*)d_in[1];
    } else {
        W  = (const float*)d_in[0];
        la = (const float*)d_in[1];
    }
    float* out = (float*)d_out;

    k1_exp_transpose<<<dim3(32, 32), dim3(32, 8)>>>(W);
    k2_colnorm<<<4, 256>>>();
    k3_alpha<<<BB, 256>>>(la);
    k4_gemm<<<dim3(16, 4, KS), 128>>>();
    k5_reduce<<<128, 256>>>(out);
}

// round 7
// speedup vs baseline: 1.5058x; 1.5058x over previous
#include <cuda_runtime.h>
#include <cuda_bf16.h>

#define NN 1024
#define BB 128
#define KS 8              // split-K factor
#define KCHUNK (NN / KS)  // 128
#define NT 64             // i-tile per block in k4

// Scratch (static device globals; no allocation)
__device__ __align__(16) __nv_bfloat16 g_EWthi[NN * NN];  // hi(exp(W[i][k])) stored [k][i]
__device__ __align__(16) __nv_bfloat16 g_EWtlo[NN * NN];  // lo part
__device__ __align__(16) __nv_bfloat16 g_Athi[BB * NN];   // hi(At[b][k])  row-major [b][k]
__device__ __align__(16) __nv_bfloat16 g_Atlo[BB * NN];
__device__ float g_part[32 * NN];        // per-i-tile column partial sums
__device__ float g_c[NN];                // c[k] = log sum_i exp(W[i][k])
__device__ float g_m[BB];                // m[b]
__device__ float g_ps[KS * BB * NN];     // split-K partial sums

// ---------------------------------------------------------------------------
// PTX helpers
// ---------------------------------------------------------------------------
__device__ __forceinline__ unsigned smem_u32(const void* p) {
    return (unsigned)__cvta_generic_to_shared(p);
}
__device__ __forceinline__ void ldm_x4(unsigned r[4], const void* p) {
    asm volatile("ldmatrix.sync.aligned.m8n8.x4.shared.b16 {%0,%1,%2,%3}, [%4];"
                 : "=r"(r[0]), "=r"(r[1]), "=r"(r[2]), "=r"(r[3])
                 : "r"(smem_u32(p)));
}
__device__ __forceinline__ void ldm_x4t(unsigned r[4], const void* p) {
    asm volatile("ldmatrix.sync.aligned.m8n8.x4.trans.shared.b16 {%0,%1,%2,%3}, [%4];"
                 : "=r"(r[0]), "=r"(r[1]), "=r"(r[2]), "=r"(r[3])
                 : "r"(smem_u32(p)));
}
__device__ __forceinline__ void mma_bf16(float c[4], const unsigned a[4], const unsigned b[2]) {
    asm volatile(
        "mma.sync.aligned.m16n8k16.row.col.f32.bf16.bf16.f32 "
        "{%0,%1,%2,%3}, {%4,%5,%6,%7}, {%8,%9}, {%0,%1,%2,%3};"
        : "+f"(c[0]), "+f"(c[1]), "+f"(c[2]), "+f"(c[3])
        : "r"(a[0]), "r"(a[1]), "r"(a[2]), "r"(a[3]), "r"(b[0]), "r"(b[1]));
}

// ---------------------------------------------------------------------------
// k1: tiled transpose + exp -> bf16 hi/lo + column partial sums
// grid (32 k-tiles, 32 i-tiles), block (32, 8)
// ---------------------------------------------------------------------------
__global__ void k1_exp_transpose(const float* __restrict__ W) {
    __shared__ float sm[32][33];
    const int k0 = blockIdx.x * 32, i0 = blockIdx.y * 32;
    const int tx = threadIdx.x, ty = threadIdx.y;

#pragma unroll
    for (int j = 0; j < 4; j++) {
        int il = ty + 8 * j;
        sm[il][tx] = __expf(W[(size_t)(i0 + il) * NN + (k0 + tx)]);
    }
    __syncthreads();

#pragma unroll
    for (int j = 0; j < 4; j++) {
        int kl = ty + 8 * j;
        float e = sm[tx][kl];  // = exp(W[i0+tx][k0+kl])
        __nv_bfloat16 h = __float2bfloat16(e);
        float lo = e - __bfloat162float(h);
        g_EWthi[(size_t)(k0 + kl) * NN + (i0 + tx)] = h;
        g_EWtlo[(size_t)(k0 + kl) * NN + (i0 + tx)] = __float2bfloat16(lo);
    }

    float s = 0.f;
#pragma unroll
    for (int j = 0; j < 4; j++) s += sm[ty + 8 * j][tx];

    __shared__ float red[8][32];
    red[ty][tx] = s;
    __syncthreads();
    if (ty == 0) {
        float t = 0.f;
#pragma unroll
        for (int y = 0; y < 8; y++) t += red[y][tx];
        g_part[blockIdx.y * NN + (k0 + tx)] = t;
    }
}

// ---------------------------------------------------------------------------
// k2: c[k] = log(sum of 32 partials)
// ---------------------------------------------------------------------------
__global__ void k2_colnorm() {
    int k = blockIdx.x * 256 + threadIdx.x;
    float s = 0.f;
#pragma unroll
    for (int t = 0; t < 32; t++) s += g_part[t * NN + k];
    g_c[k] = logf(s);
}

// ---------------------------------------------------------------------------
// k3: per-batch m[b]; At[b][k] = exp(la-c-m) split into bf16 hi/lo, row-major
// grid BB, block 256 (4 k per thread)
// ---------------------------------------------------------------------------
__global__ void k3_alpha(const float* __restrict__ la) {
    const int b = blockIdx.x, t = threadIdx.x;
    float4 lv = reinterpret_cast<const float4*>(la + (size_t)b * NN)[t];
    float4 cv = reinterpret_cast<const float4*>(g_c)[t];
    float v0 = lv.x - cv.x, v1 = lv.y - cv.y, v2 = lv.z - cv.z, v3 = lv.w - cv.w;
    float mx = fmaxf(fmaxf(v0, v1), fmaxf(v2, v3));
#pragma unroll
    for (int o = 16; o > 0; o >>= 1) mx = fmaxf(mx, __shfl_xor_sync(0xffffffffu, mx, o));
    __shared__ float wred[8];
    if ((t & 31) == 0) wred[t >> 5] = mx;
    __syncthreads();
    float m2 = wred[0];
#pragma unroll
    for (int w = 1; w < 8; w++) m2 = fmaxf(m2, wred[w]);

    float e0 = __expf(v0 - m2), e1 = __expf(v1 - m2);
    float e2 = __expf(v2 - m2), e3 = __expf(v3 - m2);
    __nv_bfloat16 h0 = __float2bfloat16(e0), h1 = __float2bfloat16(e1);
    __nv_bfloat16 h2 = __float2bfloat16(e2), h3 = __float2bfloat16(e3);
    __nv_bfloat162 hh01, hh23, ll01, ll23;
    hh01.x = h0; hh01.y = h1; hh23.x = h2; hh23.y = h3;
    ll01.x = __float2bfloat16(e0 - __bfloat162float(h0));
    ll01.y = __float2bfloat16(e1 - __bfloat162float(h1));
    ll23.x = __float2bfloat16(e2 - __bfloat162float(h2));
    ll23.y = __float2bfloat16(e3 - __bfloat162float(h3));

    const int k = 4 * t;
    *reinterpret_cast<__nv_bfloat162*>(&g_Athi[(size_t)b * NN + k])     = hh01;
    *reinterpret_cast<__nv_bfloat162*>(&g_Athi[(size_t)b * NN + k + 2]) = hh23;
    *reinterpret_cast<__nv_bfloat162*>(&g_Atlo[(size_t)b * NN + k])     = ll01;
    *reinterpret_cast<__nv_bfloat162*>(&g_Atlo[(size_t)b * NN + k + 2]) = ll23;
    if (t == 0) g_m[b] = m2;
}

// ---------------------------------------------------------------------------
// k4: tensor-core split-K GEMM partial via bf16 hi/lo 3-pass mma
// block: 128 b x 64 i x (KCHUNK=128) k, 256 threads = 8 warps (4m x 2n)
// warp tile 32(b) x 32(i). grid (16 i-tiles, KS)
// ---------------------------------------------------------------------------
__global__ void __launch_bounds__(256) k4_gemm() {
    __shared__ __nv_bfloat16 sAh[128][40], sAl[128][40];  // [b][k], pad 8
    __shared__ __nv_bfloat16 sBh[32][72],  sBl[32][72];   // [k][i], pad 8
    const int i0 = blockIdx.x * NT;
    const int kbase = blockIdx.y * KCHUNK;
    const int tid = threadIdx.x;
    const int lane = tid & 31, wid = tid >> 5;
    const int wm = wid & 3, wn = wid >> 2;

    uint4 rah[2], ral[2], rbh, rbl;

#define LOADG(ks)                                                                  \
    {                                                                              \
        const int kk0 = kbase + (ks) * 32;                                         \
        _Pragma("unroll") for (int q = 0; q < 2; q++) {                            \
            int idx = tid + q * 256;                                               \
            int r = idx >> 2, c = idx & 3;                                         \
            rah[q] = *reinterpret_cast<const uint4*>(                              \
                &g_Athi[(size_t)r * NN + kk0 + c * 8]);                            \
            ral[q] = *reinterpret_cast<const uint4*>(                              \
                &g_Atlo[(size_t)r * NN + kk0 + c * 8]);                            \
        }                                                                          \
        {                                                                          \
            int r = tid >> 3, c = tid & 7;                                         \
            rbh = *reinterpret_cast<const uint4*>(                                 \
                &g_EWthi[(size_t)(kk0 + r) * NN + i0 + c * 8]);                    \
            rbl = *reinterpret_cast<const uint4*>(                                 \
                &g_EWtlo[(size_t)(kk0 + r) * NN + i0 + c * 8]);                    \
        }                                                                          \
    }

#define STORES()                                                                   \
    {                                                                              \
        _Pragma("unroll") for (int q = 0; q < 2; q++) {                            \
            int idx = tid + q * 256;                                               \
            int r = idx >> 2, c = idx & 3;                                         \
            *reinterpret_cast<uint4*>(&sAh[r][c * 8]) = rah[q];                    \
            *reinterpret_cast<uint4*>(&sAl[r][c * 8]) = ral[q];                    \
        }                                                                          \
        {                                                                          \
            int r = tid >> 3, c = tid & 7;                                         \
            *reinterpret_cast<uint4*>(&sBh[r][c * 8]) = rbh;                       \
            *reinterpret_cast<uint4*>(&sBl[r][c * 8]) = rbl;                       \
        }                                                                          \
    }

    LOADG(0);
    STORES();
    __syncthreads();

    float acc[2][4][4];
#pragma unroll
    for (int mt = 0; mt < 2; mt++)
#pragma unroll
        for (int nt = 0; nt < 4; nt++)
#pragma unroll
            for (int e = 0; e < 4; e++) acc[mt][nt][e] = 0.f;

    const int lr = lane & 15, lh = (lane >> 4) * 8;

#pragma unroll 1
    for (int s = 0; s < 4; s++) {
        if (s < 3) LOADG(s + 1);

#pragma unroll
        for (int ks = 0; ks < 2; ks++) {
            unsigned ah[2][4], al[2][4], bh[4][2], bl[4][2];
#pragma unroll
            for (int mt = 0; mt < 2; mt++) {
                const int row = 32 * wm + 16 * mt + lr;
                ldm_x4(ah[mt], &sAh[row][ks * 16 + lh]);
                ldm_x4(al[mt], &sAl[row][ks * 16 + lh]);
            }
#pragma unroll
            for (int p = 0; p < 2; p++) {
                unsigned t4[4];
                const int row = ks * 16 + lr;
                const int col = 32 * wn + p * 16 + lh;
                ldm_x4t(t4, &sBh[row][col]);
                bh[2 * p][0] = t4[0]; bh[2 * p][1] = t4[1];
                bh[2 * p + 1][0] = t4[2]; bh[2 * p + 1][1] = t4[3];
                ldm_x4t(t4, &sBl[row][col]);
                bl[2 * p][0] = t4[0]; bl[2 * p][1] = t4[1];
                bl[2 * p + 1][0] = t4[2]; bl[2 * p + 1][1] = t4[3];
            }
#pragma unroll
            for (int mt = 0; mt < 2; mt++)
#pragma unroll
                for (int nt = 0; nt < 4; nt++) {
                    mma_bf16(acc[mt][nt], ah[mt], bh[nt]);
                    mma_bf16(acc[mt][nt], ah[mt], bl[nt]);
                    mma_bf16(acc[mt][nt], al[mt], bh[nt]);
                }
        }

        if (s < 3) {
            __syncthreads();
            STORES();
            __syncthreads();
        }
    }

    // write fp32 partials
    float* ps = g_ps + (size_t)blockIdx.y * BB * NN;
    const int g = lane >> 2, tg = lane & 3;
#pragma unroll
    for (int mt = 0; mt < 2; mt++)
#pragma unroll
        for (int nt = 0; nt < 4; nt++) {
            const int b = 32 * wm + 16 * mt + g;
            const int i = i0 + 32 * wn + 8 * nt + 2 * tg;
            float2 lo2 = make_float2(acc[mt][nt][0], acc[mt][nt][1]);
            float2 hi2 = make_float2(acc[mt][nt][2], acc[mt][nt][3]);
            *reinterpret_cast<float2*>(&ps[(size_t)b * NN + i]) = lo2;
            *reinterpret_cast<float2*>(&ps[(size_t)(b + 8) * NN + i]) = hi2;
        }
#undef LOADG
#undef STORES
}

// ---------------------------------------------------------------------------
// k5: reduce KS partials, out = log(sum) + m[b]
// ---------------------------------------------------------------------------
__global__ void k5_reduce(float* __restrict__ out) {
    const int idx = blockIdx.x * 256 + threadIdx.x;  // float4 index, 32768 total
    const int b = idx >> 8;
    const float4* p = reinterpret_cast<const float4*>(g_ps);
    float4 s = p[idx];
#pragma unroll
    for (int z = 1; z < KS; z++) {
        float4 v = p[(size_t)z * (BB * NN / 4) + idx];
        s.x += v.x; s.y += v.y; s.z += v.z; s.w += v.w;
    }
    const float mb = g_m[b];
    float4 o;
    o.x = logf(s.x) + mb;
    o.y = logf(s.y) + mb;
    o.z = logf(s.z) + mb;
    o.w = logf(s.w) + mb;
    reinterpret_cast<float4*>(out)[idx] = o;
}

// ---------------------------------------------------------------------------
extern "C" void kernel_launch(void* const* d_in, const int* in_sizes, int n_in,
                              void* d_out, int out_size) {
    const float* la;
    const float* W;
    if (in_sizes[0] == BB * NN) {
        la = (const float*)d_in[0];
        W  = (const float*)d_in[1];
    } else {
        W  = (const float*)d_in[0];
        la = (const float*)d_in[1];
    }
    float* out = (float*)d_out;

    k1_exp_transpose<<<dim3(32, 32), dim3(32, 8)>>>(W);
    k2_colnorm<<<4, 256>>>();
    k3_alpha<<<BB, 256>>>(la);
    k4_gemm<<<dim3(16, KS), 256>>>();
    k5_reduce<<<128, 256>>>(out);
}